// round 7
// baseline (speedup 1.0000x reference)
#include <cuda_runtime.h>

// InputEmbedding: out[b,t,v,d] = features[b,t,v] * W[v,d] + b[v,d] + pos[b,t,d]
// pos = concat( tod_table[bar_in_day[b,t]] (d 0..127),
//               dow_table[day_of_week[b]]  (d 128..159),
//               dom_table[day_of_month[b]] (d 160..191),
//               doy_table[day_of_year[b]]  (d 192..255) )
//
// B=64, T=288, V=24, D=256. Output 453 MB fp32 -> DRAM-store bound target.
//
// Thread owns d4 (one float4 column chunk) and VG=4 consecutive v's:
//  - W/b for the 4 v's in registers (loop-invariant)
//  - x for the 4 v's loaded as ONE float4 (V contiguous in features)
//  - pos gathered once per t, shared across the 4 v's
//  - non-tod warps (d4>=32) have pos fully loop-invariant (depends on b only)

#define Tlen  288
#define Vn    24
#define D4n   64            // D/4
#define VG    4             // v's per thread
#define TCH   48            // t's per block
#define TG    4             // thread groups (tid>>6), each covers TCH/TG t's
#define TPG   (TCH / TG)    // 12 t's per group

__global__ __launch_bounds__(256)
void input_embedding_kernel(
    const float*  __restrict__ features,     // (B,T,V)
    const int*    __restrict__ bar_in_day,   // (B,T)
    const int*    __restrict__ day_of_week,  // (B,)
    const int*    __restrict__ day_of_month, // (B,)
    const int*    __restrict__ day_of_year,  // (B,)
    const float4* __restrict__ W4,           // (V, 64)
    const float4* __restrict__ b4,           // (V, 64)
    const float4* __restrict__ tod4,         // (288, 32)
    const float4* __restrict__ dow4,         // (7, 8)
    const float4* __restrict__ dom4,         // (32, 8)
    const float4* __restrict__ doy4,         // (367, 16)
    float4*       __restrict__ out)          // (B,T,V,64)
{
    const int tid = threadIdx.x;
    const int d4  = tid & (D4n - 1);        // 0..63
    const int g   = tid >> 6;               // 0..3
    const int b   = blockIdx.x;             // 0..63
    const int v0  = blockIdx.z * VG;        // 0,4,...,20

    // loop-invariant: W/b for the 4 v's this thread covers
    float4 w[VG], bi[VG];
    #pragma unroll
    for (int j = 0; j < VG; j++) {
        w[j]  = __ldg(&W4[(v0 + j) * D4n + d4]);
        bi[j] = __ldg(&b4[(v0 + j) * D4n + d4]);
    }

    const bool tod_lane = (d4 < 32);        // uniform per warp
    float4 pc = make_float4(0.f, 0.f, 0.f, 0.f);
    if (!tod_lane) {
        if (d4 < 40)      pc = __ldg(&dow4[__ldg(&day_of_week[b])  * 8  + (d4 - 32)]);
        else if (d4 < 48) pc = __ldg(&dom4[__ldg(&day_of_month[b]) * 8  + (d4 - 40)]);
        else              pc = __ldg(&doy4[__ldg(&day_of_year[b])  * 16 + (d4 - 48)]);
    }

    const int t0  = blockIdx.y * TCH + g * TPG;
    const int bt0 = b * Tlen + t0;

    const float4* fptr = (const float4*)(features + bt0 * Vn + v0); // stride Vn/4=6 float4s per t
    const int*    bidp = bar_in_day + bt0;
    float4*       optr = out + ((long)bt0 * Vn + v0) * D4n + d4;

    #pragma unroll 3
    for (int i = 0; i < TPG; i++) {
        const float4 x4 = __ldg(fptr + i * (Vn / 4));   // x for v0..v0+3

        float4 p = pc;
        if (tod_lane) {
            const int bid = __ldg(bidp + i);
            p = __ldg(&tod4[bid * 32 + d4]);
        }

        float4* ob = optr + (long)i * (Vn * D4n);
        const float xs[VG] = {x4.x, x4.y, x4.z, x4.w};
        #pragma unroll
        for (int j = 0; j < VG; j++) {
            float4 o;
            o.x = fmaf(xs[j], w[j].x, bi[j].x) + p.x;
            o.y = fmaf(xs[j], w[j].y, bi[j].y) + p.y;
            o.z = fmaf(xs[j], w[j].z, bi[j].z) + p.z;
            o.w = fmaf(xs[j], w[j].w, bi[j].w) + p.w;
            __stcs(ob + j * D4n, o);        // streaming: output never re-read
        }
    }
}

extern "C" void kernel_launch(void* const* d_in, const int* in_sizes, int n_in,
                              void* d_out, int out_size)
{
    const float* features     = (const float*)d_in[0];
    const int*   bar_in_day   = (const int*)  d_in[1];
    const int*   day_of_week  = (const int*)  d_in[2];
    const int*   day_of_month = (const int*)  d_in[3];
    const int*   day_of_year  = (const int*)  d_in[4];
    const float* W            = (const float*)d_in[5];
    const float* bvec         = (const float*)d_in[6];
    const float* tod          = (const float*)d_in[7];
    const float* dow          = (const float*)d_in[8];
    const float* dom          = (const float*)d_in[9];
    const float* doy          = (const float*)d_in[10];

    dim3 grid(64, Tlen / TCH, Vn / VG);    // (64, 6, 6) = 2304 blocks
    input_embedding_kernel<<<grid, 256>>>(
        features, bar_in_day, day_of_week, day_of_month, day_of_year,
        (const float4*)W, (const float4*)bvec,
        (const float4*)tod, (const float4*)dow,
        (const float4*)dom, (const float4*)doy,
        (float4*)d_out);
}

// round 8
// speedup vs baseline: 1.0673x; 1.0673x over previous
#include <cuda_runtime.h>

// InputEmbedding: out[b,t,v,d] = features[b,t,v] * W[v,d] + b[v,d] + pos[b,t,d]
// pos = concat( tod_table[bar_in_day[b,t]] (d 0..127),
//               dow_table[day_of_week[b]]  (d 128..159),
//               dom_table[day_of_month[b]] (d 160..191),
//               doy_table[day_of_year[b]]  (d 192..255) )
//
// B=64, T=288, V=24, D=256. Output 453 MB fp32 -> DRAM-write bound (~6.1 TB/s).
//
// Thread owns d4 and VG=2 consecutive v's: W/b in regs (16), x as one float2,
// pos gathered once per t and shared across the 2 v's. VG=2 (not 4) keeps
// regs ~40 so occupancy stays high for tail/drain overlap.

#define Tlen  288
#define Vn    24
#define D4n   64            // D/4
#define VG    2             // v's per thread
#define TCH   32            // t's per block
#define TPG   8             // t's per thread group (TCH / 4 groups)

__global__ __launch_bounds__(256)
void input_embedding_kernel(
    const float*  __restrict__ features,     // (B,T,V)
    const int*    __restrict__ bar_in_day,   // (B,T)
    const int*    __restrict__ day_of_week,  // (B,)
    const int*    __restrict__ day_of_month, // (B,)
    const int*    __restrict__ day_of_year,  // (B,)
    const float4* __restrict__ W4,           // (V, 64)
    const float4* __restrict__ b4,           // (V, 64)
    const float4* __restrict__ tod4,         // (288, 32)
    const float4* __restrict__ dow4,         // (7, 8)
    const float4* __restrict__ dom4,         // (32, 8)
    const float4* __restrict__ doy4,         // (367, 16)
    float4*       __restrict__ out)          // (B,T,V,64)
{
    const int tid = threadIdx.x;
    const int d4  = tid & (D4n - 1);        // 0..63
    const int g   = tid >> 6;               // 0..3
    const int b   = blockIdx.x;             // 0..63
    const int v0  = blockIdx.z * VG;        // 0,2,...,22

    // loop-invariant: W/b for the 2 v's this thread covers (16 regs)
    float4 w0  = __ldg(&W4[(v0 + 0) * D4n + d4]);
    float4 w1  = __ldg(&W4[(v0 + 1) * D4n + d4]);
    float4 bi0 = __ldg(&b4[(v0 + 0) * D4n + d4]);
    float4 bi1 = __ldg(&b4[(v0 + 1) * D4n + d4]);

    const bool tod_lane = (d4 < 32);        // uniform per warp
    float4 pc = make_float4(0.f, 0.f, 0.f, 0.f);
    if (!tod_lane) {
        if (d4 < 40)      pc = __ldg(&dow4[__ldg(&day_of_week[b])  * 8  + (d4 - 32)]);
        else if (d4 < 48) pc = __ldg(&dom4[__ldg(&day_of_month[b]) * 8  + (d4 - 40)]);
        else              pc = __ldg(&doy4[__ldg(&day_of_year[b])  * 16 + (d4 - 48)]);
    }

    const int t0  = blockIdx.y * TCH + g * TPG;
    const int bt0 = b * Tlen + t0;

    const float2* fptr = (const float2*)(features + bt0 * Vn + v0); // stride 12 float2/t
    const int*    bidp = bar_in_day + bt0;
    float4*       optr = out + ((long)bt0 * Vn + v0) * D4n + d4;

    #pragma unroll 4
    for (int i = 0; i < TPG; i++) {
        const float2 x2 = __ldg(fptr + i * (Vn / 2));   // x for v0, v0+1

        float4 p = pc;
        if (tod_lane) {
            const int bid = __ldg(bidp + i);
            p = __ldg(&tod4[bid * 32 + d4]);
        }

        float4* ob = optr + (long)i * (Vn * D4n);

        float4 o0, o1;
        o0.x = fmaf(x2.x, w0.x, bi0.x) + p.x;
        o0.y = fmaf(x2.x, w0.y, bi0.y) + p.y;
        o0.z = fmaf(x2.x, w0.z, bi0.z) + p.z;
        o0.w = fmaf(x2.x, w0.w, bi0.w) + p.w;
        o1.x = fmaf(x2.y, w1.x, bi1.x) + p.x;
        o1.y = fmaf(x2.y, w1.y, bi1.y) + p.y;
        o1.z = fmaf(x2.y, w1.z, bi1.z) + p.z;
        o1.w = fmaf(x2.y, w1.w, bi1.w) + p.w;

        __stcs(ob,       o0);   // streaming: output never re-read
        __stcs(ob + D4n, o1);
    }
}

extern "C" void kernel_launch(void* const* d_in, const int* in_sizes, int n_in,
                              void* d_out, int out_size)
{
    const float* features     = (const float*)d_in[0];
    const int*   bar_in_day   = (const int*)  d_in[1];
    const int*   day_of_week  = (const int*)  d_in[2];
    const int*   day_of_month = (const int*)  d_in[3];
    const int*   day_of_year  = (const int*)  d_in[4];
    const float* W            = (const float*)d_in[5];
    const float* bvec         = (const float*)d_in[6];
    const float* tod          = (const float*)d_in[7];
    const float* dow          = (const float*)d_in[8];
    const float* dom          = (const float*)d_in[9];
    const float* doy          = (const float*)d_in[10];

    dim3 grid(64, Tlen / TCH, Vn / VG);    // (64, 9, 12) = 6912 blocks
    input_embedding_kernel<<<grid, 256>>>(
        features, bar_in_day, day_of_week, day_of_month, day_of_year,
        (const float4*)W, (const float4*)bvec,
        (const float4*)tod, (const float4*)dow,
        (const float4*)dom, (const float4*)doy,
        (float4*)d_out);
}